// round 6
// baseline (speedup 1.0000x reference)
#include <cuda_runtime.h>
#include <cuda_bf16.h>
#include <cstdint>

#define BB 64
#define SS 512
#define II 256
#define HH 512
#define CC 10

// ---------------- scratch ----------------
__device__ float g_pre0[(size_t)BB * SS * HH];          // GEMM0 out (fp32)
__device__ float g_pre1[(size_t)BB * SS * HH];          // GEMM1 out (fp32)
__device__ __nv_bfloat16 g_h0hi[(size_t)BB * SS * HH];  // layer0 h, split hi
__device__ __nv_bfloat16 g_h0lo[(size_t)BB * SS * HH];  // layer0 h, split lo
__device__ __nv_bfloat16 g_h1hi[(size_t)BB * SS * HH];
__device__ __nv_bfloat16 g_h1lo[(size_t)BB * SS * HH];
__device__ int g_flags[2 * 4 * 32];                     // [layer][bg][jg] = steps done

// ---------------- helpers ----------------
__device__ __forceinline__ uint32_t pk2(float e0, float e1) {
    uint32_t r; asm("cvt.rn.bf16x2.f32 %0, %1, %2;" : "=r"(r) : "f"(e1), "f"(e0)); return r;
}
__device__ __forceinline__ void split2(float2 v, uint32_t& h, uint32_t& l) {
    h = pk2(v.x, v.y);
    float f0 = __uint_as_float(h << 16);
    float f1 = __uint_as_float(h & 0xffff0000u);
    l = pk2(v.x - f0, v.y - f1);
}
__device__ __forceinline__ void split4(float4 v, uint32_t& h0, uint32_t& h1,
                                       uint32_t& l0, uint32_t& l1) {
    split2(make_float2(v.x, v.y), h0, l0);
    split2(make_float2(v.z, v.w), h1, l1);
}
__device__ __forceinline__ void mma16(float* d, const uint32_t* a, const uint32_t* b) {
    asm volatile("mma.sync.aligned.m16n8k16.row.col.f32.bf16.bf16.f32 "
                 "{%0,%1,%2,%3},{%4,%5,%6,%7},{%8,%9},{%0,%1,%2,%3};"
                 : "+f"(d[0]), "+f"(d[1]), "+f"(d[2]), "+f"(d[3])
                 : "r"(a[0]), "r"(a[1]), "r"(a[2]), "r"(a[3]), "r"(b[0]), "r"(b[1]));
}
__device__ __forceinline__ int ld_acq(const int* p) {
    int v; asm volatile("ld.acquire.gpu.global.s32 %0, [%1];" : "=r"(v) : "l"(p) : "memory");
    return v;
}
__device__ __forceinline__ void st_rel(int* p, int v) {
    asm volatile("st.release.gpu.global.s32 [%0], %1;" :: "l"(p), "r"(v) : "memory");
}

// ---------------- GEMM: out[m][n] = sum_k A[m][k]*W[n][k] + b1[n]+b2[n] --------
// CTA tile 64x64, BK=32, 8 warps (2m x 4n), warp 32x16. Split-bf16, 3 MMAs per
// k16. Register double-buffering: next tile's LDGs issued before current MMA.
#define GP 20   // k-pair stride (16 + 4 pad)

template<bool PACKED>
__global__ __launch_bounds__(256, 2) void gemm_bf16(const float* __restrict__ A,
                                                    const __nv_bfloat16* __restrict__ Ahg,
                                                    const __nv_bfloat16* __restrict__ Alg,
                                                    const float* __restrict__ W,
                                                    const float* __restrict__ b1,
                                                    const float* __restrict__ b2,
                                                    float* __restrict__ out,
                                                    int K)
{
    __shared__ uint32_t Ah[64 * GP], Al[64 * GP], Bh[64 * GP], Bl[64 * GP];

    const int m0 = blockIdx.x * 64, n0 = blockIdx.y * 64;
    const int tid = threadIdx.x, lane = tid & 31, wp = tid >> 5;
    const int gid = lane >> 2, tg = lane & 3;
    const int wm = wp >> 2, wn = wp & 3;

    float acc[2][2][4];
#pragma unroll
    for (int mi = 0; mi < 2; mi++)
#pragma unroll
        for (int ni = 0; ni < 2; ni++)
#pragma unroll
            for (int c = 0; c < 4; c++) acc[mi][ni][c] = 0.f;

    // staging registers
    float4 va[2], vb[2];
    uint4 pvh, pvl;
    const int r_p = tid >> 2, q_p = tid & 3;           // PACKED indices
    const int r_u = tid >> 3, kq_u = tid & 7;          // unpacked (with +256 second half)

    // prologue loads (k0 = 0)
    if (PACKED) {
        size_t off = (size_t)(m0 + r_p) * K + q_p * 8;
        pvh = *(const uint4*)(Ahg + off);
        pvl = *(const uint4*)(Alg + off);
    } else {
        va[0] = *(const float4*)(A + (size_t)(m0 + r_u) * K + kq_u * 4);
        va[1] = *(const float4*)(A + (size_t)(m0 + r_u + 32) * K + kq_u * 4);
    }
    vb[0] = *(const float4*)(W + (size_t)(n0 + r_u) * K + kq_u * 4);
    vb[1] = *(const float4*)(W + (size_t)(n0 + r_u + 32) * K + kq_u * 4);

    const int NI = K / 32;
    for (int it = 0; it < NI; it++) {
        if (it > 0) __syncthreads();
        // store staged regs into SMEM (split)
        if (PACKED) {
            *(uint4*)&Ah[r_p * GP + q_p * 4] = pvh;
            *(uint4*)&Al[r_p * GP + q_p * 4] = pvl;
        } else {
#pragma unroll
            for (int i = 0; i < 2; i++) {
                uint32_t h0, h1, l0, l1; split4(va[i], h0, h1, l0, l1);
                int o = (r_u + i * 32) * GP + kq_u * 2;
                Ah[o] = h0; Ah[o + 1] = h1; Al[o] = l0; Al[o + 1] = l1;
            }
        }
#pragma unroll
        for (int i = 0; i < 2; i++) {
            uint32_t h0, h1, l0, l1; split4(vb[i], h0, h1, l0, l1);
            int o = (r_u + i * 32) * GP + kq_u * 2;
            Bh[o] = h0; Bh[o + 1] = h1; Bl[o] = l0; Bl[o + 1] = l1;
        }
        __syncthreads();

        // prefetch next tile while MMAs run
        if (it + 1 < NI) {
            int k0 = (it + 1) * 32;
            if (PACKED) {
                size_t off = (size_t)(m0 + r_p) * K + k0 + q_p * 8;
                pvh = *(const uint4*)(Ahg + off);
                pvl = *(const uint4*)(Alg + off);
            } else {
                va[0] = *(const float4*)(A + (size_t)(m0 + r_u) * K + k0 + kq_u * 4);
                va[1] = *(const float4*)(A + (size_t)(m0 + r_u + 32) * K + k0 + kq_u * 4);
            }
            vb[0] = *(const float4*)(W + (size_t)(n0 + r_u) * K + k0 + kq_u * 4);
            vb[1] = *(const float4*)(W + (size_t)(n0 + r_u + 32) * K + k0 + kq_u * 4);
        }

#pragma unroll
        for (int kc = 0; kc < 2; kc++) {
            const int kb = kc * 8;
            uint32_t ahi[2][4], alo[2][4];
#pragma unroll
            for (int mi = 0; mi < 2; mi++) {
                int rb = wm * 32 + mi * 16;
                int o0 = (rb + gid) * GP + kb + tg;
                int o1 = (rb + gid + 8) * GP + kb + tg;
                ahi[mi][0] = Ah[o0]; ahi[mi][1] = Ah[o1];
                ahi[mi][2] = Ah[o0 + 4]; ahi[mi][3] = Ah[o1 + 4];
                alo[mi][0] = Al[o0]; alo[mi][1] = Al[o1];
                alo[mi][2] = Al[o0 + 4]; alo[mi][3] = Al[o1 + 4];
            }
#pragma unroll
            for (int ni = 0; ni < 2; ni++) {
                int ob = (wn * 16 + ni * 8 + gid) * GP + kb + tg;
                uint32_t bhi[2] = { Bh[ob], Bh[ob + 4] };
                uint32_t blo[2] = { Bl[ob], Bl[ob + 4] };
#pragma unroll
                for (int mi = 0; mi < 2; mi++) {
                    mma16(acc[mi][ni], ahi[mi], bhi);
                    mma16(acc[mi][ni], ahi[mi], blo);
                    mma16(acc[mi][ni], alo[mi], bhi);
                }
            }
        }
    }

#pragma unroll
    for (int ni = 0; ni < 2; ni++) {
        int col = n0 + wn * 16 + ni * 8 + tg * 2;
        float z0 = b1[col] + b2[col];
        float z1 = b1[col + 1] + b2[col + 1];
#pragma unroll
        for (int mi = 0; mi < 2; mi++) {
            int r0 = m0 + wm * 32 + mi * 16 + gid;
            float2 v0 = { acc[mi][ni][0] + z0, acc[mi][ni][1] + z1 };
            float2 v1 = { acc[mi][ni][2] + z0, acc[mi][ni][3] + z1 };
            *(float2*)(out + (size_t)r0 * HH + col) = v0;
            *(float2*)(out + (size_t)(r0 + 8) * HH + col) = v1;
        }
    }
}

// ---------------- Recurrence: h_t = tanh(pre_t + h_{t-1} @ W_hh^T) -------------
// 128 CTAs = 4 batch-groups (16 batches) x 32 j-slices (16 outputs).
// W fragments live in REGISTERS (loaded once). A fragments LDG'd straight from
// the packed bf16 h arrays (storage layout == fragment layout). Per-producer
// flags: consumer warp waits only on the 4 producers covering its 64-k slice.
__global__ __launch_bounds__(256) void rnn_recur(const float* __restrict__ pre,
                                                 const float* __restrict__ whh,
                                                 __nv_bfloat16* __restrict__ hhi,
                                                 __nv_bfloat16* __restrict__ hlo,
                                                 int* __restrict__ flags)
{
    __shared__ float Rd[8 * 256];        // [warp][16 b][16 j]

    const int tid = threadIdx.x, lane = tid & 31, wp = tid >> 5;
    const int gid = lane >> 2, tg = lane & 3;
    const int bg = blockIdx.x & 3;
    const int jg = blockIdx.x >> 2;
    const int b0 = bg * 16, jbase = jg * 16;
    const int rb = tid >> 4, rj = tid & 15;

    // ---- W fragments into registers (once) ----
    uint32_t wfh[4][2][2], wfl[4][2][2];
#pragma unroll
    for (int kc = 0; kc < 4; kc++) {
        int kp = wp * 32 + kc * 8 + tg;          // k-pair index
#pragma unroll
        for (int nt = 0; nt < 2; nt++) {
            const float* wr = whh + (size_t)(jbase + nt * 8 + gid) * HH;
            float2 p0 = *(const float2*)(wr + 2 * kp);
            float2 p1 = *(const float2*)(wr + 2 * kp + 8);
            split2(p0, wfh[kc][nt][0], wfl[kc][nt][0]);
            split2(p1, wfh[kc][nt][1], wfl[kc][nt][1]);
        }
    }

    const uint32_t* Hh32 = (const uint32_t*)hhi;
    const uint32_t* Hl32 = (const uint32_t*)hlo;
    int* myflag = flags + bg * 32 + jg;
    int* pflag  = flags + bg * 32 + wp * 4 + lane;   // valid for lane < 4

    for (int t = 0; t < SS; t++) {
        float pf = __ldg(pre + ((size_t)(b0 + rb) * SS + t) * HH + jbase + rj);

        uint32_t ahi[4][4], alo[4][4];
        if (t > 0) {
            if (lane < 4) {
                while (ld_acq(pflag) < t) { }
            }
            __syncwarp();
            size_t ra = ((size_t)(b0 + gid) * SS + (t - 1)) * (HH / 2);
            size_t rc = ((size_t)(b0 + gid + 8) * SS + (t - 1)) * (HH / 2);
#pragma unroll
            for (int kc = 0; kc < 4; kc++) {
                int kp = wp * 32 + kc * 8 + tg;
                ahi[kc][0] = __ldcg(Hh32 + ra + kp);
                ahi[kc][1] = __ldcg(Hh32 + rc + kp);
                ahi[kc][2] = __ldcg(Hh32 + ra + kp + 4);
                ahi[kc][3] = __ldcg(Hh32 + rc + kp + 4);
                alo[kc][0] = __ldcg(Hl32 + ra + kp);
                alo[kc][1] = __ldcg(Hl32 + rc + kp);
                alo[kc][2] = __ldcg(Hl32 + ra + kp + 4);
                alo[kc][3] = __ldcg(Hl32 + rc + kp + 4);
            }
        } else {
#pragma unroll
            for (int kc = 0; kc < 4; kc++)
#pragma unroll
                for (int i = 0; i < 4; i++) { ahi[kc][i] = 0; alo[kc][i] = 0; }
        }

        float acc[2][4];
#pragma unroll
        for (int nt = 0; nt < 2; nt++)
#pragma unroll
            for (int c = 0; c < 4; c++) acc[nt][c] = 0.f;

#pragma unroll
        for (int kc = 0; kc < 4; kc++) {
#pragma unroll
            for (int nt = 0; nt < 2; nt++) {
                mma16(acc[nt], ahi[kc], wfh[kc][nt]);
                mma16(acc[nt], ahi[kc], wfl[kc][nt]);
                mma16(acc[nt], alo[kc], wfh[kc][nt]);
            }
        }

        // partial sums -> SMEM
#pragma unroll
        for (int nt = 0; nt < 2; nt++) {
            int c0 = wp * 256 + gid * 16 + nt * 8 + tg * 2;
            Rd[c0]       = acc[nt][0];
            Rd[c0 + 1]   = acc[nt][1];
            Rd[c0 + 128] = acc[nt][2];
            Rd[c0 + 129] = acc[nt][3];
        }
        __syncthreads();

        // reduce 8 k-partitions, tanh, split-store
        {
            float s = 0.f;
#pragma unroll
            for (int r = 0; r < 8; r++) s += Rd[r * 256 + rb * 16 + rj];
            float h = tanhf(pf + s);
            __nv_bfloat16 hb = __float2bfloat16(h);
            __nv_bfloat16 lb = __float2bfloat16(h - __bfloat162float(hb));
            size_t oidx = ((size_t)(b0 + rb) * SS + t) * HH + jbase + rj;
            hhi[oidx] = hb;
            hlo[oidx] = lb;
        }
        __syncthreads();
        if (tid == 0) st_rel(myflag, t + 1);
    }
}

// ---------------- FC head ----------------
__global__ void fc_kernel(const __nv_bfloat16* __restrict__ hhi,
                          const __nv_bfloat16* __restrict__ hlo,
                          const float* __restrict__ wfc,
                          const float* __restrict__ bfc,
                          float* __restrict__ out)
{
    const int b = blockIdx.x;
    const int c = threadIdx.x >> 5;
    const int lane = threadIdx.x & 31;
    const size_t base = ((size_t)b * SS + (SS - 1)) * HH;
    float acc = 0.f;
    for (int j = lane; j < HH; j += 32) {
        float h = __bfloat162float(hhi[base + j]) + __bfloat162float(hlo[base + j]);
        acc += h * wfc[c * HH + j];
    }
#pragma unroll
    for (int o = 16; o; o >>= 1) acc += __shfl_down_sync(0xffffffffu, acc, o);
    if (lane == 0) out[b * CC + c] = acc + bfc[c];
}

// ---------------- launch ----------------
extern "C" void kernel_launch(void* const* d_in, const int* in_sizes, int n_in,
                              void* d_out, int out_size)
{
    const float* x     = (const float*)d_in[0];
    const float* w_ih0 = (const float*)d_in[1];
    const float* w_hh0 = (const float*)d_in[2];
    const float* b_ih0 = (const float*)d_in[3];
    const float* b_hh0 = (const float*)d_in[4];
    const float* w_ih1 = (const float*)d_in[5];
    const float* w_hh1 = (const float*)d_in[6];
    const float* b_ih1 = (const float*)d_in[7];
    const float* b_hh1 = (const float*)d_in[8];
    const float* w_fc  = (const float*)d_in[9];
    const float* b_fc  = (const float*)d_in[10];
    float* out = (float*)d_out;

    float *pre0, *pre1;
    __nv_bfloat16 *h0hi, *h0lo, *h1hi, *h1lo;
    int* flags;
    cudaGetSymbolAddress((void**)&pre0, g_pre0);
    cudaGetSymbolAddress((void**)&pre1, g_pre1);
    cudaGetSymbolAddress((void**)&h0hi, g_h0hi);
    cudaGetSymbolAddress((void**)&h0lo, g_h0lo);
    cudaGetSymbolAddress((void**)&h1hi, g_h1hi);
    cudaGetSymbolAddress((void**)&h1lo, g_h1lo);
    cudaGetSymbolAddress((void**)&flags, g_flags);

    cudaMemsetAsync(flags, 0, 2 * 4 * 32 * sizeof(int));

    dim3 gemm_grid(BB * SS / 64, HH / 64);

    // Layer 0
    gemm_bf16<false><<<gemm_grid, 256>>>(x, nullptr, nullptr, w_ih0, b_ih0, b_hh0, pre0, II);
    rnn_recur<<<128, 256>>>(pre0, w_hh0, h0hi, h0lo, flags);

    // Layer 1 (A operand already split)
    gemm_bf16<true><<<gemm_grid, 256>>>(nullptr, h0hi, h0lo, w_ih1, b_ih1, b_hh1, pre1, HH);
    rnn_recur<<<128, 256>>>(pre1, w_hh1, h1hi, h1lo, flags + 4 * 32);

    // Head
    fc_kernel<<<BB, CC * 32>>>(h1hi, h1lo, w_fc, b_fc, out);
}

// round 7
// speedup vs baseline: 3.1042x; 3.1042x over previous
#include <cuda_runtime.h>
#include <cuda_bf16.h>
#include <cstdint>

#define BB 64
#define SS 512
#define II 256
#define HH 512
#define CC 10

// ---------------- scratch ----------------
__device__ __nv_bfloat16 g_xhi[(size_t)BB * SS * II];   // x split hi
__device__ __nv_bfloat16 g_xlo[(size_t)BB * SS * II];   // x split lo
__device__ __nv_bfloat16 g_h0hi[(size_t)BB * SS * HH];  // layer0 h split
__device__ __nv_bfloat16 g_h0lo[(size_t)BB * SS * HH];
__device__ __nv_bfloat16 g_h1hi[(size_t)BB * SS * HH];  // layer1 h split
__device__ __nv_bfloat16 g_h1lo[(size_t)BB * SS * HH];
__device__ int g_flags[2 * 4 * SS];                     // [layer][bg][t] counters (to 32)

// ---------------- helpers ----------------
__device__ __forceinline__ uint32_t pk2(float e0, float e1) {
    uint32_t r; asm("cvt.rn.bf16x2.f32 %0, %1, %2;" : "=r"(r) : "f"(e1), "f"(e0)); return r;
}
__device__ __forceinline__ void split2(float2 v, uint32_t& h, uint32_t& l) {
    h = pk2(v.x, v.y);
    float f0 = __uint_as_float(h << 16);
    float f1 = __uint_as_float(h & 0xffff0000u);
    l = pk2(v.x - f0, v.y - f1);
}
__device__ __forceinline__ void split4(float4 v, uint32_t& h0, uint32_t& h1,
                                       uint32_t& l0, uint32_t& l1) {
    split2(make_float2(v.x, v.y), h0, l0);
    split2(make_float2(v.z, v.w), h1, l1);
}
__device__ __forceinline__ void mma16(float* d, const uint32_t* a, const uint32_t* b) {
    asm volatile("mma.sync.aligned.m16n8k16.row.col.f32.bf16.bf16.f32 "
                 "{%0,%1,%2,%3},{%4,%5,%6,%7},{%8,%9},{%0,%1,%2,%3};"
                 : "+f"(d[0]), "+f"(d[1]), "+f"(d[2]), "+f"(d[3])
                 : "r"(a[0]), "r"(a[1]), "r"(a[2]), "r"(a[3]), "r"(b[0]), "r"(b[1]));
}
__device__ __forceinline__ int ld_acq(const int* p) {
    int v; asm volatile("ld.acquire.gpu.global.s32 %0, [%1];" : "=r"(v) : "l"(p) : "memory");
    return v;
}
__device__ __forceinline__ void red_rel(int* p, int v) {
    asm volatile("red.release.gpu.global.add.s32 [%0], %1;" :: "l"(p), "r"(v) : "memory");
}

// ---------------- x pre-split (fp32 -> bf16 hi/lo pairs) ----------------
__global__ void split_x_kernel(const float* __restrict__ x,
                               __nv_bfloat16* __restrict__ xhi,
                               __nv_bfloat16* __restrict__ xlo)
{
    size_t i = (size_t)blockIdx.x * 256 + threadIdx.x;    // float4 index
    float4 v = *(const float4*)(x + 4 * i);
    uint32_t h0, h1, l0, l1; split4(v, h0, h1, l0, l1);
    *(uint2*)((uint32_t*)xhi + 2 * i) = make_uint2(h0, h1);
    *(uint2*)((uint32_t*)xlo + 2 * i) = make_uint2(l0, l1);
}

// ---------------- fused 2-layer RNN ----------------
// 256 CTAs: layer = bx>>7; inner 128 = 4 batch-groups(16b) x 32 j-slices(16j).
// Layer L, step t: h_t = tanh(b_ih + b_hh + in_t @ W_ih^T + h_{t-1} @ W_hh^T)
//   layer0: in = x (K=256), layer1: in = h0_t (K=512, waits on layer0 flag).
// W fragments in registers (loaded once); h/in staged cooperatively to SMEM.
#define RP 260     // k-pair stride for 512-k stage (256 + 4 pad)
#define XP 132     // k-pair stride for 256-k stage (128 + 4 pad)
#define FSMEM_BYTES ((4 * 16 * RP) * 4 + 8 * 256 * 4)

__global__ __launch_bounds__(256, 2) void rnn_fused(
    const __nv_bfloat16* __restrict__ xhi, const __nv_bfloat16* __restrict__ xlo,
    const float* __restrict__ w_ih0, const float* __restrict__ w_hh0,
    const float* __restrict__ b_ih0, const float* __restrict__ b_hh0,
    const float* __restrict__ w_ih1, const float* __restrict__ w_hh1,
    const float* __restrict__ b_ih1, const float* __restrict__ b_hh1,
    __nv_bfloat16* __restrict__ h0hi, __nv_bfloat16* __restrict__ h0lo,
    __nv_bfloat16* __restrict__ h1hi, __nv_bfloat16* __restrict__ h1lo,
    int* __restrict__ flags)
{
    extern __shared__ uint32_t smu[];
    uint32_t* Php = smu;                 // h_prev hi [16][RP]
    uint32_t* Plp = smu + 16 * RP;       // h_prev lo
    uint32_t* Ihp = smu + 2 * 16 * RP;   // input hi  [16][RP or XP]
    uint32_t* Ilp = smu + 3 * 16 * RP;   // input lo
    float*    Rd  = (float*)(smu + 4 * 16 * RP);  // [8][16][16]

    const int tid = threadIdx.x, lane = tid & 31, wp = tid >> 5;
    const int gid = lane >> 2, tg = lane & 3;
    const int layer = blockIdx.x >> 7;
    const int inner = blockIdx.x & 127;
    const int bg = inner & 3, jg = inner >> 2;
    const int b0 = bg * 16, jbase = jg * 16;
    const int rb = tid >> 4, rj = tid & 15;

    const float* whh = layer ? w_hh1 : w_hh0;
    const float* wih = layer ? w_ih1 : w_ih0;
    const float* bi  = layer ? b_ih1 : b_ih0;
    const float* bh  = layer ? b_hh1 : b_hh0;
    __nv_bfloat16* ohi = layer ? h1hi : h0hi;
    __nv_bfloat16* olo = layer ? h1lo : h0lo;
    const uint32_t* ihg = layer ? (const uint32_t*)h0hi : (const uint32_t*)xhi;
    const uint32_t* ilg = layer ? (const uint32_t*)h0lo : (const uint32_t*)xlo;
    int* fown = flags + layer * 4 * SS + bg * SS;
    int* fdep = flags + bg * SS;               // layer0 flags (used when layer==1)

    const float bias = bi[jbase + rj] + bh[jbase + rj];

    // ---- W_hh fragments into registers (once) ----
    uint32_t whf[4][2][2], wlf[4][2][2];
#pragma unroll
    for (int kc = 0; kc < 4; kc++) {
        int kp = wp * 32 + kc * 8 + tg;
#pragma unroll
        for (int nt = 0; nt < 2; nt++) {
            const float* wr = whh + (size_t)(jbase + nt * 8 + gid) * HH;
            split2(*(const float2*)(wr + 2 * kp),     whf[kc][nt][0], wlf[kc][nt][0]);
            split2(*(const float2*)(wr + 2 * kp + 8), whf[kc][nt][1], wlf[kc][nt][1]);
        }
    }
    // ---- W_ih fragments (layer0: K=256 -> 2 kc; layer1: K=512 -> 4 kc) ----
    const int KCI = layer ? 4 : 2;
    const int KIN = layer ? II /*unused*/ : II;
    (void)KIN;
    uint32_t uhf[4][2][2], ulf[4][2][2];
#pragma unroll
    for (int kc = 0; kc < 4; kc++) {
        if (kc < KCI) {
            int kp = wp * (layer ? 32 : 16) + kc * 8 + tg;
            int stride = layer ? HH : II;
#pragma unroll
            for (int nt = 0; nt < 2; nt++) {
                const float* wr = wih + (size_t)(jbase + nt * 8 + gid) * stride;
                split2(*(const float2*)(wr + 2 * kp),     uhf[kc][nt][0], ulf[kc][nt][0]);
                split2(*(const float2*)(wr + 2 * kp + 8), uhf[kc][nt][1], ulf[kc][nt][1]);
            }
        }
    }

    const uint32_t* Oh32 = (const uint32_t*)ohi;
    const uint32_t* Ol32 = (const uint32_t*)olo;
    const int IP = layer ? RP : XP;
    const int irow = layer ? (HH / 2) : (II / 2);   // u32 row length of input

    for (int t = 0; t < SS; t++) {
        // ---- wait on dependencies (single poller) ----
        if (tid == 0) {
            if (t > 0) { while (ld_acq(fown + t - 1) < 32) { } }
            if (layer) { while (ld_acq(fdep + t) < 32) { } }
        }
        __syncthreads();

        // ---- stage h_prev (own layer, t-1) ----
        if (t > 0) {
#pragma unroll
            for (int i = 0; i < 4; i++) {
                int f = tid + i * 256;
                int b = f >> 6, q = f & 63;
                size_t off = ((size_t)(b0 + b) * SS + (t - 1)) * (HH / 2) + q * 4;
                *(uint4*)&Php[b * RP + q * 4] = __ldcg((const uint4*)(Oh32 + off));
                *(uint4*)&Plp[b * RP + q * 4] = __ldcg((const uint4*)(Ol32 + off));
            }
        } else {
#pragma unroll
            for (int i = 0; i < 4; i++) {
                int f = tid + i * 256;
                int b = f >> 6, q = f & 63;
                uint4 z = make_uint4(0, 0, 0, 0);
                *(uint4*)&Php[b * RP + q * 4] = z;
                *(uint4*)&Plp[b * RP + q * 4] = z;
            }
        }
        // ---- stage input (layer1: h0_t; layer0: x_t) ----
        if (layer) {
#pragma unroll
            for (int i = 0; i < 4; i++) {
                int f = tid + i * 256;
                int b = f >> 6, q = f & 63;
                size_t off = ((size_t)(b0 + b) * SS + t) * (HH / 2) + q * 4;
                *(uint4*)&Ihp[b * RP + q * 4] = __ldcg((const uint4*)(ihg + off));
                *(uint4*)&Ilp[b * RP + q * 4] = __ldcg((const uint4*)(ilg + off));
            }
        } else {
#pragma unroll
            for (int i = 0; i < 2; i++) {
                int f = tid + i * 256;
                int b = f >> 5, q = f & 31;
                size_t off = ((size_t)(b0 + b) * SS + t) * (II / 2) + q * 4;
                *(uint4*)&Ihp[b * XP + q * 4] = __ldg((const uint4*)(ihg + off));
                *(uint4*)&Ilp[b * XP + q * 4] = __ldg((const uint4*)(ilg + off));
            }
        }
        __syncthreads();

        float acc[2][4];
#pragma unroll
        for (int nt = 0; nt < 2; nt++)
#pragma unroll
            for (int c = 0; c < 4; c++) acc[nt][c] = 0.f;

        // ---- h_prev @ W_hh (4 kc) ----
#pragma unroll
        for (int kc = 0; kc < 4; kc++) {
            const int kb = wp * 32 + kc * 8 + tg;
            int o0 = gid * RP + kb;
            int o1 = (gid + 8) * RP + kb;
            uint32_t ahi[4] = { Php[o0], Php[o1], Php[o0 + 4], Php[o1 + 4] };
            uint32_t alo[4] = { Plp[o0], Plp[o1], Plp[o0 + 4], Plp[o1 + 4] };
#pragma unroll
            for (int nt = 0; nt < 2; nt++) {
                mma16(acc[nt], ahi, whf[kc][nt]);
                mma16(acc[nt], ahi, wlf[kc][nt]);
                mma16(acc[nt], alo, whf[kc][nt]);
            }
        }
        // ---- input @ W_ih (KCI kc) ----
#pragma unroll
        for (int kc = 0; kc < 4; kc++) {
            if (kc < KCI) {
                const int kb = wp * (layer ? 32 : 16) + kc * 8 + tg;
                int o0 = gid * IP + kb;
                int o1 = (gid + 8) * IP + kb;
                uint32_t ahi[4] = { Ihp[o0], Ihp[o1], Ihp[o0 + 4], Ihp[o1 + 4] };
                uint32_t alo[4] = { Ilp[o0], Ilp[o1], Ilp[o0 + 4], Ilp[o1 + 4] };
#pragma unroll
                for (int nt = 0; nt < 2; nt++) {
                    mma16(acc[nt], ahi, uhf[kc][nt]);
                    mma16(acc[nt], ahi, ulf[kc][nt]);
                    mma16(acc[nt], alo, uhf[kc][nt]);
                }
            }
        }

        // ---- partials -> SMEM ----
#pragma unroll
        for (int nt = 0; nt < 2; nt++) {
            int c0 = wp * 256 + gid * 16 + nt * 8 + tg * 2;
            Rd[c0]       = acc[nt][0];
            Rd[c0 + 1]   = acc[nt][1];
            Rd[c0 + 128] = acc[nt][2];
            Rd[c0 + 129] = acc[nt][3];
        }
        __syncthreads();

        // ---- reduce 8 k-partitions, tanh, split-store ----
        {
            float s = 0.f;
#pragma unroll
            for (int r = 0; r < 8; r++) s += Rd[r * 256 + rb * 16 + rj];
            float h = tanhf(bias + s);
            __nv_bfloat16 hb = __float2bfloat16(h);
            __nv_bfloat16 lb = __float2bfloat16(h - __bfloat162float(hb));
            size_t oidx = ((size_t)(b0 + rb) * SS + t) * HH + jbase + rj;
            ohi[oidx] = hb;
            olo[oidx] = lb;
        }
        __syncthreads();
        if (tid == 0) red_rel(fown + t, 1);
    }
}

// ---------------- FC head ----------------
__global__ void fc_kernel(const __nv_bfloat16* __restrict__ hhi,
                          const __nv_bfloat16* __restrict__ hlo,
                          const float* __restrict__ wfc,
                          const float* __restrict__ bfc,
                          float* __restrict__ out)
{
    const int b = blockIdx.x;
    const int c = threadIdx.x >> 5;
    const int lane = threadIdx.x & 31;
    const size_t base = ((size_t)b * SS + (SS - 1)) * HH;
    float acc = 0.f;
    for (int j = lane; j < HH; j += 32) {
        float h = __bfloat162float(hhi[base + j]) + __bfloat162float(hlo[base + j]);
        acc += h * wfc[c * HH + j];
    }
#pragma unroll
    for (int o = 16; o; o >>= 1) acc += __shfl_down_sync(0xffffffffu, acc, o);
    if (lane == 0) out[b * CC + c] = acc + bfc[c];
}

// ---------------- launch ----------------
extern "C" void kernel_launch(void* const* d_in, const int* in_sizes, int n_in,
                              void* d_out, int out_size)
{
    const float* x     = (const float*)d_in[0];
    const float* w_ih0 = (const float*)d_in[1];
    const float* w_hh0 = (const float*)d_in[2];
    const float* b_ih0 = (const float*)d_in[3];
    const float* b_hh0 = (const float*)d_in[4];
    const float* w_ih1 = (const float*)d_in[5];
    const float* w_hh1 = (const float*)d_in[6];
    const float* b_ih1 = (const float*)d_in[7];
    const float* b_hh1 = (const float*)d_in[8];
    const float* w_fc  = (const float*)d_in[9];
    const float* b_fc  = (const float*)d_in[10];
    float* out = (float*)d_out;

    __nv_bfloat16 *xhi, *xlo, *h0hi, *h0lo, *h1hi, *h1lo;
    int* flags;
    cudaGetSymbolAddress((void**)&xhi,  g_xhi);
    cudaGetSymbolAddress((void**)&xlo,  g_xlo);
    cudaGetSymbolAddress((void**)&h0hi, g_h0hi);
    cudaGetSymbolAddress((void**)&h0lo, g_h0lo);
    cudaGetSymbolAddress((void**)&h1hi, g_h1hi);
    cudaGetSymbolAddress((void**)&h1lo, g_h1lo);
    cudaGetSymbolAddress((void**)&flags, g_flags);

    cudaFuncSetAttribute(rnn_fused,
                         cudaFuncAttributeMaxDynamicSharedMemorySize, FSMEM_BYTES);

    cudaMemsetAsync(flags, 0, 2 * 4 * SS * sizeof(int));

    // split x once (B*S*I/4 float4s, 256/block)
    split_x_kernel<<<(BB * SS * II / 4) / 256, 256>>>(x, xhi, xlo);

    // fused 2-layer pipelined recurrence (both GEMMs folded in)
    rnn_fused<<<256, 256, FSMEM_BYTES>>>(xhi, xlo,
                                         w_ih0, w_hh0, b_ih0, b_hh0,
                                         w_ih1, w_hh1, b_ih1, b_hh1,
                                         h0hi, h0lo, h1hi, h1lo, flags);

    // head
    fc_kernel<<<BB, CC * 32>>>(h1hi, h1lo, w_fc, b_fc, out);
}

// round 8
// speedup vs baseline: 3.7150x; 1.1968x over previous
#include <cuda_runtime.h>
#include <cuda_bf16.h>
#include <cstdint>

#define BB 64
#define SS 512
#define II 256
#define HH 512
#define CC 10
#define NPROD 16

// ---------------- scratch ----------------
__device__ __nv_bfloat16 g_h0hi[(size_t)BB * SS * HH];
__device__ __nv_bfloat16 g_h0lo[(size_t)BB * SS * HH];
__device__ __nv_bfloat16 g_h1hi[(size_t)BB * SS * HH];
__device__ __nv_bfloat16 g_h1lo[(size_t)BB * SS * HH];
__device__ int g_flags[2 * 4 * SS];        // [layer][bg][t] counters (to NPROD)

// ---------------- helpers ----------------
__device__ __forceinline__ uint32_t pk2(float e0, float e1) {
    uint32_t r; asm("cvt.rn.bf16x2.f32 %0, %1, %2;" : "=r"(r) : "f"(e1), "f"(e0)); return r;
}
__device__ __forceinline__ void split2(float2 v, uint32_t& h, uint32_t& l) {
    h = pk2(v.x, v.y);
    float f0 = __uint_as_float(h << 16);
    float f1 = __uint_as_float(h & 0xffff0000u);
    l = pk2(v.x - f0, v.y - f1);
}
__device__ __forceinline__ void split4(float4 v, uint32_t& h0, uint32_t& h1,
                                       uint32_t& l0, uint32_t& l1) {
    split2(make_float2(v.x, v.y), h0, l0);
    split2(make_float2(v.z, v.w), h1, l1);
}
__device__ __forceinline__ void mma16(float* d, const uint32_t* a, const uint32_t* b) {
    asm volatile("mma.sync.aligned.m16n8k16.row.col.f32.bf16.bf16.f32 "
                 "{%0,%1,%2,%3},{%4,%5,%6,%7},{%8,%9},{%0,%1,%2,%3};"
                 : "+f"(d[0]), "+f"(d[1]), "+f"(d[2]), "+f"(d[3])
                 : "r"(a[0]), "r"(a[1]), "r"(a[2]), "r"(a[3]), "r"(b[0]), "r"(b[1]));
}
__device__ __forceinline__ int ld_acq(const int* p) {
    int v; asm volatile("ld.acquire.gpu.global.s32 %0, [%1];" : "=r"(v) : "l"(p) : "memory");
    return v;
}
__device__ __forceinline__ void red_rel(int* p, int v) {
    asm volatile("red.release.gpu.global.add.s32 [%0], %1;" :: "l"(p), "r"(v) : "memory");
}

// ---------------- fused 2-layer RNN ----------------
// 128 CTAs (1/SM): layer = bx>>6; inner 64 = 4 batch-groups(16b) x 16 j-slices(32j).
// h_t = tanh(b_ih + b_hh + in_t @ W_ih^T + h_{t-1} @ W_hh^T)
//   layer0: in = x_t (fp32, split inline, K=256); layer1: in = h0_t (K=512).
// 8 warps = 4 k-parts(128k) x 2 j-halves(16j). All W fragments in registers.
#define RP 260      // k-pair stride, 512-k stage (256 + 4)
#define XP 132      // k-pair stride, 256-k stage (128 + 4)
#define RDW 33      // reduce row stride
#define FSMEM_BYTES ((4 * 16 * RP + 64 * RDW) * 4)

__global__ __launch_bounds__(256, 1) void rnn_fused(
    const float* __restrict__ x,
    const float* __restrict__ w_ih0, const float* __restrict__ w_hh0,
    const float* __restrict__ b_ih0, const float* __restrict__ b_hh0,
    const float* __restrict__ w_ih1, const float* __restrict__ w_hh1,
    const float* __restrict__ b_ih1, const float* __restrict__ b_hh1,
    __nv_bfloat16* __restrict__ h0hi, __nv_bfloat16* __restrict__ h0lo,
    __nv_bfloat16* __restrict__ h1hi, __nv_bfloat16* __restrict__ h1lo,
    int* __restrict__ flags)
{
    extern __shared__ uint32_t smu[];
    uint32_t* Php = smu;                 // h_prev hi [16][RP]
    uint32_t* Plp = smu + 16 * RP;       // h_prev lo
    uint32_t* Ihp = smu + 2 * 16 * RP;   // input hi  [16][RP or XP]
    uint32_t* Ilp = smu + 3 * 16 * RP;   // input lo
    float*    Rd  = (float*)(smu + 4 * 16 * RP);  // [4*16][RDW]

    const int tid = threadIdx.x, lane = tid & 31, wp = tid >> 5;
    const int gid = lane >> 2, tg = lane & 3;
    const int wk = wp & 3, wj = wp >> 2;           // k-part, j-half
    const int layer = blockIdx.x >> 6;
    const int inner = blockIdx.x & 63;
    const int bg = inner & 3, jg = inner >> 2;
    const int b0 = bg * 16, jbase = jg * 32;
    const int rb = tid >> 4, rjp = tid & 15;       // output mapping: batch, j-pair

    const float* whh = layer ? w_hh1 : w_hh0;
    const float* wih = layer ? w_ih1 : w_ih0;
    const float* bi  = layer ? b_ih1 : b_ih0;
    const float* bh  = layer ? b_hh1 : b_hh0;
    uint32_t* Ohw = (uint32_t*)(layer ? h1hi : h0hi);
    uint32_t* Olw = (uint32_t*)(layer ? h1lo : h0lo);
    const uint32_t* ihg = (const uint32_t*)h0hi;   // layer1 input
    const uint32_t* ilg = (const uint32_t*)h0lo;
    int* fown = flags + layer * 4 * SS + bg * SS;
    int* fdep = flags + bg * SS;

    const float bias0 = bi[jbase + 2 * rjp]     + bh[jbase + 2 * rjp];
    const float bias1 = bi[jbase + 2 * rjp + 1] + bh[jbase + 2 * rjp + 1];

    // ---- W_hh fragments -> registers (once): 8 kc x 2 nt ----
    uint32_t whf[8][2][2], wlf[8][2][2];
#pragma unroll
    for (int kc = 0; kc < 8; kc++) {
        int kp = wk * 64 + kc * 8 + tg;
#pragma unroll
        for (int nt = 0; nt < 2; nt++) {
            const float* wr = whh + (size_t)(jbase + wj * 16 + nt * 8 + gid) * HH;
            split2(*(const float2*)(wr + 2 * kp),     whf[kc][nt][0], wlf[kc][nt][0]);
            split2(*(const float2*)(wr + 2 * kp + 8), whf[kc][nt][1], wlf[kc][nt][1]);
        }
    }
    // ---- W_ih fragments (layer0: 4 kc over K=256; layer1: 8 kc over K=512) ----
    uint32_t uhf[8][2][2], ulf[8][2][2];
    if (layer) {
#pragma unroll
        for (int kc = 0; kc < 8; kc++) {
            int kp = wk * 64 + kc * 8 + tg;
#pragma unroll
            for (int nt = 0; nt < 2; nt++) {
                const float* wr = wih + (size_t)(jbase + wj * 16 + nt * 8 + gid) * HH;
                split2(*(const float2*)(wr + 2 * kp),     uhf[kc][nt][0], ulf[kc][nt][0]);
                split2(*(const float2*)(wr + 2 * kp + 8), uhf[kc][nt][1], ulf[kc][nt][1]);
            }
        }
    } else {
#pragma unroll
        for (int kc = 0; kc < 4; kc++) {
            int kp = wk * 32 + kc * 8 + tg;
#pragma unroll
            for (int nt = 0; nt < 2; nt++) {
                const float* wr = wih + (size_t)(jbase + wj * 16 + nt * 8 + gid) * II;
                split2(*(const float2*)(wr + 2 * kp),     uhf[kc][nt][0], ulf[kc][nt][0]);
                split2(*(const float2*)(wr + 2 * kp + 8), uhf[kc][nt][1], ulf[kc][nt][1]);
            }
        }
    }

    for (int t = 0; t < SS; t++) {
        if (!layer) {
            // stage x_t (no dependency) while waiting; split inline
#pragma unroll
            for (int i = 0; i < 4; i++) {
                int f = tid + i * 256;
                int b = f >> 6, q = f & 63;
                float4 v = *(const float4*)(x + ((size_t)(b0 + b) * SS + t) * II + q * 4);
                uint32_t h0, h1, l0, l1; split4(v, h0, h1, l0, l1);
                *(uint2*)&Ihp[b * XP + q * 2] = make_uint2(h0, h1);
                *(uint2*)&Ilp[b * XP + q * 2] = make_uint2(l0, l1);
            }
            if (tid == 0 && t > 0) { while (ld_acq(fown + t - 1) < NPROD) { } }
            __syncthreads();
        } else {
            // parallel polls: lane0 -> own t-1, lane1 -> layer0 t
            if (tid < 2) {
                if (tid == 0) { if (t > 0) while (ld_acq(fown + t - 1) < NPROD) { } }
                else         { while (ld_acq(fdep + t) < NPROD) { } }
            }
            __syncthreads();
            // stage input h0_t
#pragma unroll
            for (int i = 0; i < 4; i++) {
                int f = tid + i * 256;
                int b = f >> 6, q = f & 63;
                size_t off = ((size_t)(b0 + b) * SS + t) * (HH / 2) + q * 4;
                *(uint4*)&Ihp[b * RP + q * 4] = __ldcg((const uint4*)(ihg + off));
                *(uint4*)&Ilp[b * RP + q * 4] = __ldcg((const uint4*)(ilg + off));
            }
        }

        // stage h_prev (own layer, t-1)
        if (t > 0) {
#pragma unroll
            for (int i = 0; i < 4; i++) {
                int f = tid + i * 256;
                int b = f >> 6, q = f & 63;
                size_t off = ((size_t)(b0 + b) * SS + (t - 1)) * (HH / 2) + q * 4;
                *(uint4*)&Php[b * RP + q * 4] = __ldcg((const uint4*)(Ohw + off));
                *(uint4*)&Plp[b * RP + q * 4] = __ldcg((const uint4*)(Olw + off));
            }
        } else {
#pragma unroll
            for (int i = 0; i < 4; i++) {
                int f = tid + i * 256;
                int b = f >> 6, q = f & 63;
                uint4 z = make_uint4(0, 0, 0, 0);
                *(uint4*)&Php[b * RP + q * 4] = z;
                *(uint4*)&Plp[b * RP + q * 4] = z;
            }
        }
        __syncthreads();

        float acc[2][4];
#pragma unroll
        for (int nt = 0; nt < 2; nt++)
#pragma unroll
            for (int c = 0; c < 4; c++) acc[nt][c] = 0.f;

        // ---- h_prev @ W_hh : 8 kc ----
#pragma unroll
        for (int kc = 0; kc < 8; kc++) {
            int kp = wk * 64 + kc * 8 + tg;
            int o0 = gid * RP + kp, o1 = (gid + 8) * RP + kp;
            uint32_t ahi[4] = { Php[o0], Php[o1], Php[o0 + 4], Php[o1 + 4] };
            uint32_t alo[4] = { Plp[o0], Plp[o1], Plp[o0 + 4], Plp[o1 + 4] };
#pragma unroll
            for (int nt = 0; nt < 2; nt++) {
                mma16(acc[nt], ahi, whf[kc][nt]);
                mma16(acc[nt], ahi, wlf[kc][nt]);
                mma16(acc[nt], alo, whf[kc][nt]);
            }
        }
        // ---- input @ W_ih ----
        if (layer) {
#pragma unroll
            for (int kc = 0; kc < 8; kc++) {
                int kp = wk * 64 + kc * 8 + tg;
                int o0 = gid * RP + kp, o1 = (gid + 8) * RP + kp;
                uint32_t ahi[4] = { Ihp[o0], Ihp[o1], Ihp[o0 + 4], Ihp[o1 + 4] };
                uint32_t alo[4] = { Ilp[o0], Ilp[o1], Ilp[o0 + 4], Ilp[o1 + 4] };
#pragma unroll
                for (int nt = 0; nt < 2; nt++) {
                    mma16(acc[nt], ahi, uhf[kc][nt]);
                    mma16(acc[nt], ahi, ulf[kc][nt]);
                    mma16(acc[nt], alo, uhf[kc][nt]);
                }
            }
        } else {
#pragma unroll
            for (int kc = 0; kc < 4; kc++) {
                int kp = wk * 32 + kc * 8 + tg;
                int o0 = gid * XP + kp, o1 = (gid + 8) * XP + kp;
                uint32_t ahi[4] = { Ihp[o0], Ihp[o1], Ihp[o0 + 4], Ihp[o1 + 4] };
                uint32_t alo[4] = { Ilp[o0], Ilp[o1], Ilp[o0 + 4], Ilp[o1 + 4] };
#pragma unroll
                for (int nt = 0; nt < 2; nt++) {
                    mma16(acc[nt], ahi, uhf[kc][nt]);
                    mma16(acc[nt], ahi, ulf[kc][nt]);
                    mma16(acc[nt], alo, uhf[kc][nt]);
                }
            }
        }

        // ---- partials -> Rd[wk*16 + b][col] ----
#pragma unroll
        for (int nt = 0; nt < 2; nt++) {
            int col = wj * 16 + nt * 8 + tg * 2;
            int r0 = (wk * 16 + gid) * RDW + col;
            int r1 = (wk * 16 + gid + 8) * RDW + col;
            Rd[r0] = acc[nt][0]; Rd[r0 + 1] = acc[nt][1];
            Rd[r1] = acc[nt][2]; Rd[r1 + 1] = acc[nt][3];
        }
        __syncthreads();

        // ---- reduce 4 k-parts, tanh, split-pack-store (2 outputs/thread) ----
        {
            float s0 = 0.f, s1 = 0.f;
#pragma unroll
            for (int r = 0; r < 4; r++) {
                int o = (r * 16 + rb) * RDW + 2 * rjp;
                s0 += Rd[o]; s1 += Rd[o + 1];
            }
            float v0 = tanhf(bias0 + s0);
            float v1 = tanhf(bias1 + s1);
            uint32_t hp, lp; split2(make_float2(v0, v1), hp, lp);
            size_t oo = ((size_t)(b0 + rb) * SS + t) * (HH / 2) + (jbase >> 1) + rjp;
            Ohw[oo] = hp;
            Olw[oo] = lp;
        }
        __syncthreads();
        if (tid == 0) red_rel(fown + t, 1);
    }
}

// ---------------- FC head ----------------
__global__ void fc_kernel(const __nv_bfloat16* __restrict__ hhi,
                          const __nv_bfloat16* __restrict__ hlo,
                          const float* __restrict__ wfc,
                          const float* __restrict__ bfc,
                          float* __restrict__ out)
{
    const int b = blockIdx.x;
    const int c = threadIdx.x >> 5;
    const int lane = threadIdx.x & 31;
    const size_t base = ((size_t)b * SS + (SS - 1)) * HH;
    float acc = 0.f;
    for (int j = lane; j < HH; j += 32) {
        float h = __bfloat162float(hhi[base + j]) + __bfloat162float(hlo[base + j]);
        acc += h * wfc[c * HH + j];
    }
#pragma unroll
    for (int o = 16; o; o >>= 1) acc += __shfl_down_sync(0xffffffffu, acc, o);
    if (lane == 0) out[b * CC + c] = acc + bfc[c];
}

// ---------------- launch ----------------
extern "C" void kernel_launch(void* const* d_in, const int* in_sizes, int n_in,
                              void* d_out, int out_size)
{
    const float* x     = (const float*)d_in[0];
    const float* w_ih0 = (const float*)d_in[1];
    const float* w_hh0 = (const float*)d_in[2];
    const float* b_ih0 = (const float*)d_in[3];
    const float* b_hh0 = (const float*)d_in[4];
    const float* w_ih1 = (const float*)d_in[5];
    const float* w_hh1 = (const float*)d_in[6];
    const float* b_ih1 = (const float*)d_in[7];
    const float* b_hh1 = (const float*)d_in[8];
    const float* w_fc  = (const float*)d_in[9];
    const float* b_fc  = (const float*)d_in[10];
    float* out = (float*)d_out;

    __nv_bfloat16 *h0hi, *h0lo, *h1hi, *h1lo;
    int* flags;
    cudaGetSymbolAddress((void**)&h0hi, g_h0hi);
    cudaGetSymbolAddress((void**)&h0lo, g_h0lo);
    cudaGetSymbolAddress((void**)&h1hi, g_h1hi);
    cudaGetSymbolAddress((void**)&h1lo, g_h1lo);
    cudaGetSymbolAddress((void**)&flags, g_flags);

    cudaFuncSetAttribute(rnn_fused,
                         cudaFuncAttributeMaxDynamicSharedMemorySize, FSMEM_BYTES);

    cudaMemsetAsync(flags, 0, 2 * 4 * SS * sizeof(int));

    rnn_fused<<<128, 256, FSMEM_BYTES>>>(x,
                                         w_ih0, w_hh0, b_ih0, b_hh0,
                                         w_ih1, w_hh1, b_ih1, b_hh1,
                                         h0hi, h0lo, h1hi, h1lo, flags);

    fc_kernel<<<BB, CC * 32>>>(h1hi, h1lo, w_fc, b_fc, out);
}